// round 2
// baseline (speedup 1.0000x reference)
#include <cuda_runtime.h>
#include <cuda_bf16.h>
#include <cstdint>

#define DINLINE __device__ __forceinline__

// ---------------- problem constants ----------------
constexpr int BQ  = 8192;   // batch rows
constexpr int HID = 1024;   // hidden
constexpr int K6  = 6144;   // packed K (6 blocks of 1024)
constexpr int N9  = 9216;   // packed N (7 sum gates + x3 + m3)

// GEMM tiling
constexpr int BM = 128, BN = 128, BK = 64, NSTAGE = 3;
constexpr int A_STAGE_BYTES = BM * BK * 2;                   // 16384
constexpr int B_STAGE_BYTES = BN * BK * 2;                   // 16384
constexpr int STAGE_BYTES   = A_STAGE_BYTES + B_STAGE_BYTES; // 32768
constexpr int SMEM_DYN      = NSTAGE * STAGE_BYTES + 1024;

constexpr int MT = BQ / BM;   // 64 m-tiles
constexpr int NT = N9 / BN;   // 72 n-tiles
constexpr int GM = 8;         // m-supertile height

// ---------------- device scratch (static globals: allowed) ----------------
__device__ __nv_bfloat16 g_A[(size_t)BQ * K6];   // 96 MB
__device__ __nv_bfloat16 g_B[(size_t)N9 * K6];   // 108 MB
__device__ float         g_C[(size_t)BQ * N9];   // 288 MB

// ---------------- PTX helpers (sm_80-class only; NO tcgen05/TMA) -----------
DINLINE uint32_t smem_u32(const void* p) {
    uint32_t a;
    asm("{ .reg .u64 t; cvta.to.shared.u64 t, %1; cvt.u32.u64 %0, t; }"
        : "=r"(a) : "l"(p));
    return a;
}

DINLINE void cp16(uint32_t dst, const void* src) {
    asm volatile("cp.async.cg.shared.global [%0], [%1], 16;" :: "r"(dst), "l"(src));
}
DINLINE void cp_commit() { asm volatile("cp.async.commit_group;" ::: "memory"); }
DINLINE void cp_wait2()  { asm volatile("cp.async.wait_group 2;" ::: "memory"); }

DINLINE void ldsm4(uint32_t& r0, uint32_t& r1, uint32_t& r2, uint32_t& r3,
                   uint32_t addr) {
    asm volatile("ldmatrix.sync.aligned.m8n8.x4.shared.b16 {%0,%1,%2,%3}, [%4];"
                 : "=r"(r0), "=r"(r1), "=r"(r2), "=r"(r3) : "r"(addr));
}

DINLINE void mma16816(float* c, const uint32_t* a, const uint32_t* b) {
    asm volatile(
        "mma.sync.aligned.m16n8k16.row.col.f32.bf16.bf16.f32 "
        "{%0,%1,%2,%3}, {%4,%5,%6,%7}, {%8,%9}, {%0,%1,%2,%3};"
        : "+f"(c[0]), "+f"(c[1]), "+f"(c[2]), "+f"(c[3])
        : "r"(a[0]), "r"(a[1]), "r"(a[2]), "r"(a[3]), "r"(b[0]), "r"(b[1]));
}

// ---------------- pack kernels ----------------
// A'' row b: [x_hi | x_lo | x_hi | m_hi | m_lo | m_hi], each block 1024 wide
__global__ void pack_A(const float* __restrict__ x, const float* __restrict__ m) {
    size_t i = (size_t)blockIdx.x * blockDim.x + threadIdx.x;
    if (i >= (size_t)BQ * HID) return;
    size_t b = i >> 10;
    int kk = (int)(i & 1023);
    float xv = x[i];
    __nv_bfloat16 xh = __float2bfloat16(xv);
    __nv_bfloat16 xl = __float2bfloat16(xv - __bfloat162float(xh));
    float mv = m[i];
    __nv_bfloat16 mh = __float2bfloat16(mv);
    __nv_bfloat16 ml = __float2bfloat16(mv - __bfloat162float(mh));
    size_t row = b * K6;
    g_A[row +        kk] = xh;
    g_A[row + 1024 + kk] = xl;
    g_A[row + 2048 + kk] = xh;
    g_A[row + 3072 + kk] = mh;
    g_A[row + 4096 + kk] = ml;
    g_A[row + 5120 + kk] = mh;
}

// B'' [N9, K6] K-major (transposed weights). blockIdx.z: 0 = w_inputs, 1 = w_m
__global__ void pack_B(const float* __restrict__ wi, const float* __restrict__ wm) {
    __shared__ float t[32][33];
    int ct = blockIdx.x;             // col tile over 8192 (256 tiles)
    int kt = blockIdx.y;             // k tile over 1024 (32 tiles)
    const float* w = blockIdx.z ? wm : wi;
    int col0 = ct * 32, k0 = kt * 32;
    int tx = threadIdx.x, ty = threadIdx.y;
    for (int r = ty; r < 32; r += 8)
        t[r][tx] = w[(size_t)(k0 + r) * 8192 + col0 + tx];
    __syncthreads();
    for (int r = ty; r < 32; r += 8) {
        int col = col0 + r;
        int kk  = k0 + tx;
        float v = t[tx][r];          // = w[kk][col]
        __nv_bfloat16 hi = __float2bfloat16(v);
        __nv_bfloat16 lo = __float2bfloat16(v - __bfloat162float(hi));
        int g = col >> 10, h = col & 1023;
        size_t n;
        int kb0, kb1, kb2;
        if (blockIdx.z == 0) {       // w_inputs -> K-blocks 0,1 = hi; 2 = lo
            n = (g == 3) ? (size_t)(7168 + h) : (size_t)((g < 3 ? g : g - 1) * 1024 + h);
            kb0 = 0; kb1 = 1024; kb2 = 2048;
        } else {                     // w_m -> K-blocks 3,4 = hi; 5 = lo
            n = (g == 3) ? (size_t)(8192 + h) : (size_t)((g < 3 ? g : g - 1) * 1024 + h);
            kb0 = 3072; kb1 = 4096; kb2 = 5120;
        }
        size_t base = n * K6;
        g_B[base + kb0 + kk] = hi;
        g_B[base + kb1 + kk] = hi;
        g_B[base + kb2 + kk] = lo;
    }
}

// ---------------- GEMM: C[8192, 9216] = A''[8192,6144] @ B''^T ----------------
__global__ __launch_bounds__(256, 2)
void gemm_kernel() {
    extern __shared__ char dsmem[];
    char* tilep = (char*)(((uintptr_t)dsmem + 1023) & ~(uintptr_t)1023);
    uint32_t tile_base = smem_u32(tilep);

    int tid = threadIdx.x;
    int wid = tid >> 5;
    int lid = tid & 31;
    int wm = (wid & 1) * 64;     // warp m-offset within tile (2 warps in m)
    int wn = (wid >> 1) * 32;    // warp n-offset within tile (4 warps in n)

    // supertile rasterization: bands of GM m-tiles sweep all n for L2 reuse
    int bid = blockIdx.x;
    int mt = (bid / (GM * NT)) * GM + (bid % GM);
    int nt = (bid / GM) % NT;
    int m0 = mt * BM;
    int n0 = nt * BN;

    int kbeg = 0, kend = K6;
    if (n0 >= 8192)       kbeg = 3072;   // m3 region: only m K-blocks
    else if (n0 >= 7168)  kend = 3072;   // x3 region: only x K-blocks
    int NK = (kend - kbeg) >> 6;

    const char* gAbase = (const char*)g_A + (size_t)m0 * (K6 * 2);
    const char* gBbase = (const char*)g_B + (size_t)n0 * (K6 * 2);

    auto fill_stage = [&](int s, int k0) {
        uint32_t baseA = tile_base + s * STAGE_BYTES;
        uint32_t baseB = baseA + A_STAGE_BYTES;
        const char* gA = gAbase + (size_t)k0 * 2;
        const char* gB = gBbase + (size_t)k0 * 2;
#pragma unroll
        for (int j = 0; j < 8; j++) {
            int ch = tid + (j << 8);           // 0..2047
            int rr = (ch >> 3) & 127;
            int cc = ch & 7;
            uint32_t off = (uint32_t)((rr << 7) + (cc << 4));
            uint32_t sw  = off ^ ((off >> 3) & 0x70);
            const char* src = ((ch < 1024) ? gA : gB) + (size_t)rr * (K6 * 2) + (cc << 4);
            cp16(((ch < 1024) ? baseA : baseB) + sw, src);
        }
    };

    float acc[4][4][4];
#pragma unroll
    for (int mf = 0; mf < 4; mf++)
#pragma unroll
        for (int nf = 0; nf < 4; nf++)
#pragma unroll
            for (int q = 0; q < 4; q++) acc[mf][nf][q] = 0.0f;

    // prologue: stages 0 and 1 in flight
    fill_stage(0, kbeg);          cp_commit();
    fill_stage(1, kbeg + BK);     cp_commit();

    // per-lane ldmatrix addressing constants
    int rowA = wm + (lid & 15);                       // + mf*16
    int kAby = ((lid >> 4) * 8) * 2;                  // + ks*32 bytes
    int rowB = wn + (lid & 7) + (lid >> 4) * 8;       // + nf2*16
    int kBby = (((lid >> 3) & 1) * 8) * 2;            // + ks*32 bytes

    for (int i = 0; i < NK; i++) {
        int s = i - (i / NSTAGE) * NSTAGE;            // i % 3
        if (i + 2 < NK) fill_stage((s + 2 >= NSTAGE) ? s + 2 - NSTAGE : s + 2,
                                   kbeg + (i + 2) * BK);
        cp_commit();
        cp_wait2();
        __syncthreads();

        uint32_t sA = tile_base + s * STAGE_BYTES;
        uint32_t sB = sA + A_STAGE_BYTES;
#pragma unroll
        for (int ks = 0; ks < 4; ks++) {
            uint32_t aF[4][4];
            uint32_t bF[4][2];
#pragma unroll
            for (int mf = 0; mf < 4; mf++) {
                uint32_t off = (uint32_t)((rowA + mf * 16) << 7);
                uint32_t addr = sA + off + (((uint32_t)(kAby + ks * 32)) ^ ((off >> 3) & 0x70));
                ldsm4(aF[mf][0], aF[mf][1], aF[mf][2], aF[mf][3], addr);
            }
#pragma unroll
            for (int nf2 = 0; nf2 < 2; nf2++) {
                uint32_t off = (uint32_t)((rowB + nf2 * 16) << 7);
                uint32_t addr = sB + off + (((uint32_t)(kBby + ks * 32)) ^ ((off >> 3) & 0x70));
                uint32_t r0, r1, r2, r3;
                ldsm4(r0, r1, r2, r3, addr);
                bF[nf2 * 2][0] = r0;  bF[nf2 * 2][1] = r1;
                bF[nf2 * 2 + 1][0] = r2;  bF[nf2 * 2 + 1][1] = r3;
            }
#pragma unroll
            for (int mf = 0; mf < 4; mf++)
#pragma unroll
                for (int nf = 0; nf < 4; nf++)
                    mma16816(acc[mf][nf], aF[mf], bF[nf]);
        }
        __syncthreads();
    }

    // epilogue: direct register -> gmem (float2 per frag-row)
    int rr = lid >> 2;
    int cc2 = (lid & 3) * 2;
#pragma unroll
    for (int mf = 0; mf < 4; mf++) {
#pragma unroll
        for (int nf = 0; nf < 4; nf++) {
            int m = m0 + wm + mf * 16 + rr;
            int n = n0 + wn + nf * 8 + cc2;
            float2 v0 = make_float2(acc[mf][nf][0], acc[mf][nf][1]);
            float2 v1 = make_float2(acc[mf][nf][2], acc[mf][nf][3]);
            *(float2*)&g_C[(size_t)m * N9 + n] = v0;
            *(float2*)&g_C[(size_t)(m + 8) * N9 + n] = v1;
        }
    }
}

// ---------------- combine: gate network ----------------
DINLINE float sigf(float v) { return 1.0f / (1.0f + expf(-v)); }

__global__ void combine_kernel(const float* __restrict__ c_prev, float* __restrict__ out) {
    size_t i = (size_t)blockIdx.x * blockDim.x + threadIdx.x;
    if (i >= (size_t)BQ * HID) return;
    size_t b = i >> 10;
    int h = (int)(i & 1023);
    const float* Cr = g_C + b * N9;
    float s0 = Cr[h],        s1 = Cr[1024 + h], s2 = Cr[2048 + h];
    float s4 = Cr[3072 + h], s5 = Cr[4096 + h], s6 = Cr[5120 + h];
    float s7 = Cr[6144 + h], x3 = Cr[7168 + h], m3 = Cr[8192 + h];

    float l10 = sigf(s0);
    float l11 = fmaxf(s1, 0.0f);
    float l12 = sigf(s2);
    float l13 = fmaxf(x3 * m3, 0.0f);
    float l14 = tanhf(s4);
    float l15 = sigf(s5);
    float l16 = tanhf(s6);
    float l17 = sigf(s7);

    float l20 = tanhf(l10 * l11);
    float l21 = tanhf(l12 + l13);
    float l22 = tanhf(l14 * l15);
    float l23 = sigf(l16 + l17);

    l20 = tanhf(l20 + c_prev[i]);
    float nc  = l20 * l21;
    float l31 = tanhf(l22 + l23);
    float nm  = tanhf(nc * l31);

    out[i] = nm;                               // new_m
    out[(size_t)BQ * HID + i] = nc;            // new_c
}

// ---------------- launch ----------------
extern "C" void kernel_launch(void* const* d_in, const int* in_sizes, int n_in,
                              void* d_out, int out_size) {
    const float* x      = (const float*)d_in[0];
    const float* m_prev = (const float*)d_in[1];
    const float* c_prev = (const float*)d_in[2];
    const float* w_m    = (const float*)d_in[3];
    const float* w_in   = (const float*)d_in[4];
    float* out = (float*)d_out;

    cudaFuncSetAttribute(gemm_kernel, cudaFuncAttributeMaxDynamicSharedMemorySize, SMEM_DYN);

    {   // pack A''
        size_t n = (size_t)BQ * HID;
        pack_A<<<(unsigned)((n + 255) / 256), 256>>>(x, m_prev);
    }
    {   // pack B'' (transpose + hi/lo split)
        dim3 grid(256, 32, 2), blk(32, 8);
        pack_B<<<grid, blk>>>(w_in, w_m);
    }
    {   // the single big GEMM
        gemm_kernel<<<MT * NT, 256, SMEM_DYN>>>();
    }
    {   // gate network
        size_t n = (size_t)BQ * HID;
        combine_kernel<<<(unsigned)((n + 255) / 256), 256>>>(c_prev, out);
    }
    (void)in_sizes; (void)n_in; (void)out_size;
}

// round 4
// speedup vs baseline: 1.0056x; 1.0056x over previous
#include <cuda_runtime.h>
#include <cuda_bf16.h>
#include <cstdint>

#define DINLINE __device__ __forceinline__

// ---------------- problem constants ----------------
constexpr int BQ  = 8192;   // batch rows
constexpr int HID = 1024;   // hidden
constexpr int K6  = 6144;   // packed K (6 blocks of 1024)
constexpr int N9  = 9216;   // packed N (7 sum gates + x3 + m3)

// GEMM tiling
constexpr int BM = 128, BN = 128, BK = 64, NSTAGE = 3;
constexpr int A_STAGE_BYTES = BM * BK * 2;                   // 16384
constexpr int B_STAGE_BYTES = BN * BK * 2;                   // 16384
constexpr int STAGE_BYTES   = A_STAGE_BYTES + B_STAGE_BYTES; // 32768
constexpr int SMEM_DYN      = NSTAGE * STAGE_BYTES + 1024;

constexpr int MT = BQ / BM;   // 64 m-tiles
constexpr int NT = N9 / BN;   // 72 n-tiles
constexpr int GM = 8;         // m-supertile height

// ---------------- device scratch (static globals: allowed) ----------------
__device__ __nv_bfloat16 g_A[(size_t)BQ * K6];   // 96 MB
__device__ __nv_bfloat16 g_B[(size_t)N9 * K6];   // 108 MB
__device__ float         g_C[(size_t)BQ * N9];   // 288 MB

// ---------------- PTX helpers (sm_80-class only) ----------------
DINLINE uint32_t smem_u32(const void* p) {
    uint32_t a;
    asm("{ .reg .u64 t; cvta.to.shared.u64 t, %1; cvt.u32.u64 %0, t; }"
        : "=r"(a) : "l"(p));
    return a;
}

DINLINE void cp16(uint32_t dst, const void* src) {
    asm volatile("cp.async.cg.shared.global [%0], [%1], 16;" :: "r"(dst), "l"(src));
}
DINLINE void cp_commit() { asm volatile("cp.async.commit_group;" ::: "memory"); }
DINLINE void cp_wait2()  { asm volatile("cp.async.wait_group 2;" ::: "memory"); }

DINLINE void ldsm4(uint32_t& r0, uint32_t& r1, uint32_t& r2, uint32_t& r3,
                   uint32_t addr) {
    asm volatile("ldmatrix.sync.aligned.m8n8.x4.shared.b16 {%0,%1,%2,%3}, [%4];"
                 : "=r"(r0), "=r"(r1), "=r"(r2), "=r"(r3) : "r"(addr));
}

DINLINE void mma16816(float* c, const uint32_t* a, const uint32_t* b) {
    asm volatile(
        "mma.sync.aligned.m16n8k16.row.col.f32.bf16.bf16.f32 "
        "{%0,%1,%2,%3}, {%4,%5,%6,%7}, {%8,%9}, {%0,%1,%2,%3};"
        : "+f"(c[0]), "+f"(c[1]), "+f"(c[2]), "+f"(c[3])
        : "r"(a[0]), "r"(a[1]), "r"(a[2]), "r"(a[3]), "r"(b[0]), "r"(b[1]));
}

// ---------------- pack kernels ----------------
// A'' row b: [x_hi | x_lo | x_hi | m_hi | m_lo | m_hi], each block 1024 wide
__global__ void pack_A(const float* __restrict__ x, const float* __restrict__ m) {
    size_t i = (size_t)blockIdx.x * blockDim.x + threadIdx.x;
    if (i >= (size_t)BQ * HID) return;
    size_t b = i >> 10;
    int kk = (int)(i & 1023);
    float xv = x[i];
    __nv_bfloat16 xh = __float2bfloat16(xv);
    __nv_bfloat16 xl = __float2bfloat16(xv - __bfloat162float(xh));
    float mv = m[i];
    __nv_bfloat16 mh = __float2bfloat16(mv);
    __nv_bfloat16 ml = __float2bfloat16(mv - __bfloat162float(mh));
    size_t row = b * K6;
    g_A[row +        kk] = xh;
    g_A[row + 1024 + kk] = xl;
    g_A[row + 2048 + kk] = xh;
    g_A[row + 3072 + kk] = mh;
    g_A[row + 4096 + kk] = ml;
    g_A[row + 5120 + kk] = mh;
}

// B'' [N9, K6] K-major (transposed weights). blockIdx.z: 0 = w_inputs, 1 = w_m
__global__ void pack_B(const float* __restrict__ wi, const float* __restrict__ wm) {
    __shared__ float t[32][33];
    int ct = blockIdx.x;             // col tile over 8192 (256 tiles)
    int kt = blockIdx.y;             // k tile over 1024 (32 tiles)
    const float* w = blockIdx.z ? wm : wi;
    int col0 = ct * 32, k0 = kt * 32;
    int tx = threadIdx.x, ty = threadIdx.y;
    for (int r = ty; r < 32; r += 8)
        t[r][tx] = w[(size_t)(k0 + r) * 8192 + col0 + tx];
    __syncthreads();
    for (int r = ty; r < 32; r += 8) {
        int col = col0 + r;
        int kk  = k0 + tx;
        float v = t[tx][r];          // = w[kk][col]
        __nv_bfloat16 hi = __float2bfloat16(v);
        __nv_bfloat16 lo = __float2bfloat16(v - __bfloat162float(hi));
        int g = col >> 10, h = col & 1023;
        size_t n;
        int kb0, kb1, kb2;
        if (blockIdx.z == 0) {       // w_inputs -> K-blocks 0,1 = hi; 2 = lo
            n = (g == 3) ? (size_t)(7168 + h) : (size_t)((g < 3 ? g : g - 1) * 1024 + h);
            kb0 = 0; kb1 = 1024; kb2 = 2048;
        } else {                     // w_m -> K-blocks 3,4 = hi; 5 = lo
            n = (g == 3) ? (size_t)(8192 + h) : (size_t)((g < 3 ? g : g - 1) * 1024 + h);
            kb0 = 3072; kb1 = 4096; kb2 = 5120;
        }
        size_t base = n * K6;
        g_B[base + kb0 + kk] = hi;
        g_B[base + kb1 + kk] = hi;
        g_B[base + kb2 + kk] = lo;
    }
}

// ---------------- GEMM: C[8192, 9216] = A''[8192,6144] @ B''^T ----------------
// 128x128 CTA tile, 4 warps, 64x64 warp tile, frag double-buffering
__global__ __launch_bounds__(128, 2)
void gemm_kernel() {
    extern __shared__ char dsmem[];
    char* tilep = (char*)(((uintptr_t)dsmem + 1023) & ~(uintptr_t)1023);
    uint32_t tile_base = smem_u32(tilep);

    int tid = threadIdx.x;
    int wid = tid >> 5;
    int lid = tid & 31;
    int wm = (wid & 1) * 64;     // warp m-offset (2 warps in m)
    int wn = (wid >> 1) * 64;    // warp n-offset (2 warps in n)

    // supertile rasterization: bands of GM m-tiles sweep all n for L2 reuse
    int bid = blockIdx.x;
    int mt = (bid / (GM * NT)) * GM + (bid % GM);
    int nt = (bid / GM) % NT;
    int m0 = mt * BM;
    int n0 = nt * BN;

    int kbeg = 0, kend = K6;
    if (n0 >= 8192)       kbeg = 3072;   // m3 region: only m K-blocks
    else if (n0 >= 7168)  kend = 3072;   // x3 region: only x K-blocks
    int NK = (kend - kbeg) >> 6;

    const char* gAbase = (const char*)g_A + (size_t)m0 * (K6 * 2);
    const char* gBbase = (const char*)g_B + (size_t)n0 * (K6 * 2);

    auto fill_stage = [&](int s, int k0) {
        uint32_t baseA = tile_base + s * STAGE_BYTES;
        uint32_t baseB = baseA + A_STAGE_BYTES;
        const char* gA = gAbase + (size_t)k0 * 2;
        const char* gB = gBbase + (size_t)k0 * 2;
#pragma unroll
        for (int j = 0; j < 16; j++) {
            int ch = tid + (j << 7);           // 0..2047
            int rr = (ch >> 3) & 127;
            int cc = ch & 7;
            uint32_t off = (uint32_t)((rr << 7) + (cc << 4));
            uint32_t sw  = off ^ ((off >> 3) & 0x70);
            const char* src = ((ch < 1024) ? gA : gB) + (size_t)rr * (K6 * 2) + (cc << 4);
            cp16(((ch < 1024) ? baseA : baseB) + sw, src);
        }
    };

    float acc[4][8][4];
#pragma unroll
    for (int mf = 0; mf < 4; mf++)
#pragma unroll
        for (int nf = 0; nf < 8; nf++)
#pragma unroll
            for (int q = 0; q < 4; q++) acc[mf][nf][q] = 0.0f;

    fill_stage(0, kbeg);          cp_commit();
    fill_stage(1, kbeg + BK);     cp_commit();

    int rowA = wm + (lid & 15);                       // + mf*16
    int kAby = ((lid >> 4) * 8) * 2;                  // + ks*32 bytes
    int rowB = wn + (lid & 7) + (lid >> 4) * 8;       // + nf2*16
    int kBby = (((lid >> 3) & 1) * 8) * 2;            // + ks*32 bytes

    uint32_t aF[2][4][4];
    uint32_t bF[2][8][2];

    auto load_frags = [&](int buf, uint32_t sA, uint32_t sB, int ks) {
#pragma unroll
        for (int mf = 0; mf < 4; mf++) {
            uint32_t off = (uint32_t)((rowA + mf * 16) << 7);
            uint32_t addr = sA + off + (((uint32_t)(kAby + ks * 32)) ^ ((off >> 3) & 0x70));
            ldsm4(aF[buf][mf][0], aF[buf][mf][1], aF[buf][mf][2], aF[buf][mf][3], addr);
        }
#pragma unroll
        for (int nf2 = 0; nf2 < 4; nf2++) {
            uint32_t off = (uint32_t)((rowB + nf2 * 16) << 7);
            uint32_t addr = sB + off + (((uint32_t)(kBby + ks * 32)) ^ ((off >> 3) & 0x70));
            uint32_t r0, r1, r2, r3;
            ldsm4(r0, r1, r2, r3, addr);
            bF[buf][nf2 * 2][0] = r0;      bF[buf][nf2 * 2][1] = r1;
            bF[buf][nf2 * 2 + 1][0] = r2;  bF[buf][nf2 * 2 + 1][1] = r3;
        }
    };

    for (int i = 0; i < NK; i++) {
        int s = i - (i / NSTAGE) * NSTAGE;            // i % 3
        if (i + 2 < NK) fill_stage((s + 2 >= NSTAGE) ? s + 2 - NSTAGE : s + 2,
                                   kbeg + (i + 2) * BK);
        cp_commit();
        cp_wait2();
        __syncthreads();

        uint32_t sA = tile_base + s * STAGE_BYTES;
        uint32_t sB = sA + A_STAGE_BYTES;

        load_frags(0, sA, sB, 0);
#pragma unroll
        for (int ks = 0; ks < 4; ks++) {
            int cur = ks & 1;
            if (ks < 3) load_frags(cur ^ 1, sA, sB, ks + 1);
#pragma unroll
            for (int mf = 0; mf < 4; mf++)
#pragma unroll
                for (int nf = 0; nf < 8; nf++)
                    mma16816(acc[mf][nf], aF[cur][mf], bF[cur][nf]);
        }
        __syncthreads();
    }

    // epilogue: direct register -> gmem (float2 per frag-row)
    int rr = lid >> 2;
    int cc2 = (lid & 3) * 2;
#pragma unroll
    for (int mf = 0; mf < 4; mf++) {
#pragma unroll
        for (int nf = 0; nf < 8; nf++) {
            int m = m0 + wm + mf * 16 + rr;
            int n = n0 + wn + nf * 8 + cc2;
            float2 v0 = make_float2(acc[mf][nf][0], acc[mf][nf][1]);
            float2 v1 = make_float2(acc[mf][nf][2], acc[mf][nf][3]);
            *(float2*)&g_C[(size_t)m * N9 + n] = v0;
            *(float2*)&g_C[(size_t)(m + 8) * N9 + n] = v1;
        }
    }
}

// ---------------- combine: gate network (float2-vectorized) ----------------
DINLINE float sigf(float v) { return 1.0f / (1.0f + expf(-v)); }

DINLINE float gate_net(float s0, float s1, float s2, float s4, float s5,
                       float s6, float s7, float x3, float m3,
                       float cp, float& nc) {
    float l10 = sigf(s0);
    float l11 = fmaxf(s1, 0.0f);
    float l12 = sigf(s2);
    float l13 = fmaxf(x3 * m3, 0.0f);
    float l14 = tanhf(s4);
    float l15 = sigf(s5);
    float l16 = tanhf(s6);
    float l17 = sigf(s7);
    float l20 = tanhf(l10 * l11);
    float l21 = tanhf(l12 + l13);
    float l22 = tanhf(l14 * l15);
    float l23 = sigf(l16 + l17);
    l20 = tanhf(l20 + cp);
    nc = l20 * l21;
    float l31 = tanhf(l22 + l23);
    return tanhf(nc * l31);
}

__global__ void combine_kernel(const float* __restrict__ c_prev, float* __restrict__ out) {
    size_t idx = (size_t)blockIdx.x * blockDim.x + threadIdx.x;
    if (idx >= (size_t)BQ * (HID / 2)) return;
    size_t b  = idx >> 9;            // row
    int    h2 = (int)(idx & 511);    // float2 index within row
    const float2* Cr = (const float2*)(g_C + b * N9) + h2;
    float2 s0 = Cr[0],        s1 = Cr[512],      s2 = Cr[1024];
    float2 s4 = Cr[1536],     s5 = Cr[2048],     s6 = Cr[2560];
    float2 s7 = Cr[3072],     x3 = Cr[3584],     m3 = Cr[4096];
    float2 cp = *((const float2*)c_prev + b * 512 + h2);

    float2 nm, nc;
    nm.x = gate_net(s0.x, s1.x, s2.x, s4.x, s5.x, s6.x, s7.x, x3.x, m3.x, cp.x, nc.x);
    nm.y = gate_net(s0.y, s1.y, s2.y, s4.y, s5.y, s6.y, s7.y, x3.y, m3.y, cp.y, nc.y);

    float2* o = (float2*)out;
    o[b * 512 + h2] = nm;                                  // new_m
    o[(size_t)BQ * 512 + b * 512 + h2] = nc;               // new_c
}

// ---------------- launch ----------------
extern "C" void kernel_launch(void* const* d_in, const int* in_sizes, int n_in,
                              void* d_out, int out_size) {
    const float* x      = (const float*)d_in[0];
    const float* m_prev = (const float*)d_in[1];
    const float* c_prev = (const float*)d_in[2];
    const float* w_m    = (const float*)d_in[3];
    const float* w_in   = (const float*)d_in[4];
    float* out = (float*)d_out;

    cudaFuncSetAttribute(gemm_kernel, cudaFuncAttributeMaxDynamicSharedMemorySize, SMEM_DYN);

    {   // pack A''
        size_t n = (size_t)BQ * HID;
        pack_A<<<(unsigned)((n + 255) / 256), 256>>>(x, m_prev);
    }
    {   // pack B'' (transpose + bf16 hi/lo split)
        dim3 grid(256, 32, 2), blk(32, 8);
        pack_B<<<grid, blk>>>(w_in, w_m);
    }
    {   // the single big GEMM
        gemm_kernel<<<MT * NT, 128, SMEM_DYN>>>();
    }
    {   // gate network
        size_t n = (size_t)BQ * (HID / 2);
        combine_kernel<<<(unsigned)((n + 255) / 256), 256>>>(c_prev, out);
    }
    (void)in_sizes; (void)n_in; (void)out_size;
}